// round 5
// baseline (speedup 1.0000x reference)
#include <cuda_runtime.h>
#include <math.h>

#define B_NO   8
#define T_LEN  10000
#define E_NUM  1000
#define I_NUM  250
#define SUB_NO 8
#define HID_NO 16
#define CBAS   30
#define T_NO   200

// output layout: final | sub_out | C_syn_e | C_syn_i
#define FINAL_OFF  0
#define SUBOUT_OFF (B_NO * T_LEN)                     // 80000
#define CE_OFF     (SUBOUT_OFF + B_NO * T_LEN * SUB_NO) // 720000
#define CI_OFF     (CE_OFF + SUB_NO * E_NUM)            // 728000

// ---------------- device scratch (no allocations allowed) ----------------
__device__ float g_Ce[SUB_NO * E_NUM];                 // softmax * exp(E_scale)
__device__ float g_Ci[SUB_NO * I_NUM];
__device__ float g_kern_e[SUB_NO * T_NO * HID_NO];     // [s][tau][h]
__device__ float g_kern_i[SUB_NO * T_NO * HID_NO];
__device__ float g_syn_e[B_NO * SUB_NO * T_LEN];       // [b][s][t]
__device__ float g_syn_i[B_NO * SUB_NO * T_LEN];

// ---------------- helpers ----------------
__device__ __forceinline__ float2 ffma2(float2 a, float2 b, float2 c) {
    union U { float2 f; unsigned long long u; };
    U A, B, C, D;
    A.f = a; B.f = b; C.f = c;
    asm("fma.rn.f32x2 %0, %1, %2, %3;" : "=l"(D.u) : "l"(A.u), "l"(B.u), "l"(C.u));
    return D.f;
}

__device__ __forceinline__ float tanh_fast(float x) {
    // tanh(x) = 1 - 2/(exp(2x)+1); exact at both saturation ends.
    float e = __expf(2.0f * x);
    return 1.0f - __fdividef(2.0f, e + 1.0f);
}

// ---------------- K0: softmax assignments (and scaled copies) ----------------
__global__ void softmax_kernel(const float* __restrict__ Cer,
                               const float* __restrict__ Cir,
                               const float* __restrict__ Es,
                               const float* __restrict__ Is,
                               float* __restrict__ out) {
    int idx = blockIdx.x * blockDim.x + threadIdx.x;
    if (idx < E_NUM) {
        float u[SUB_NO], p[SUB_NO];
        float m = -1e30f;
#pragma unroll
        for (int s = 0; s < SUB_NO; ++s) { u[s] = Cer[s * E_NUM + idx] * 10000.0f; m = fmaxf(m, u[s]); }
        float sum = 0.0f;
#pragma unroll
        for (int s = 0; s < SUB_NO; ++s) { p[s] = expf(u[s] - m); sum += p[s]; }
        float inv = 1.0f / sum;
        float sc  = expf(Es[idx]);
#pragma unroll
        for (int s = 0; s < SUB_NO; ++s) {
            float v = p[s] * inv;
            out[CE_OFF + s * E_NUM + idx] = v;
            g_Ce[s * E_NUM + idx] = v * sc;
        }
    } else if (idx < E_NUM + I_NUM) {
        int j = idx - E_NUM;
        float u[SUB_NO], p[SUB_NO];
        float m = -1e30f;
#pragma unroll
        for (int s = 0; s < SUB_NO; ++s) { u[s] = Cir[s * I_NUM + j] * 10000.0f; m = fmaxf(m, u[s]); }
        float sum = 0.0f;
#pragma unroll
        for (int s = 0; s < SUB_NO; ++s) { p[s] = expf(u[s] - m); sum += p[s]; }
        float inv = 1.0f / sum;
        float sc  = expf(Is[j]);
#pragma unroll
        for (int s = 0; s < SUB_NO; ++s) {
            float v = p[s] * inv;
            out[CI_OFF + s * I_NUM + j] = v;
            g_Ci[s * I_NUM + j] = v * sc;
        }
    }
}

// ---------------- K1: temporal kernels from cosine basis ----------------
// grid = 200 blocks (one per tau), 128 threads (one per sub*hid row)
__global__ void kern_kernel(const float* __restrict__ W_e,
                            const float* __restrict__ W_i) {
    __shared__ float bas[CBAS];
    int tau = blockIdx.x;
    if (threadIdx.x < CBAS) {
        double phi = 0.5 * M_PI * (double)threadIdx.x;
        double raw = 7.5 * log((double)tau + 1.0 + 1e-7);
        double v = 0.0;
        if (raw >= phi - M_PI && raw <= phi + M_PI)
            v = 0.5 * cos(raw - phi) + 0.5;
        bas[threadIdx.x] = (float)v;
    }
    __syncthreads();
    int r = threadIdx.x;             // 0..127
    float ae = 0.0f, ai = 0.0f;
#pragma unroll
    for (int c = 0; c < CBAS; ++c) {
        ae = fmaf(W_e[r * CBAS + c], bas[c], ae);
        ai = fmaf(W_i[r * CBAS + c], bas[c], ai);
    }
    int s = r >> 4, h = r & 15;
    g_kern_e[(s * T_NO + tau) * HID_NO + h] = ae;
    g_kern_i[(s * T_NO + tau) * HID_NO + h] = ai;
}

// ---------------- K2: synapse pooling (HBM-bound) ----------------
__device__ __forceinline__ void warp_reduce_write(float (&acc)[8][8],
                                                  float* __restrict__ dst,
                                                  int t0, int lane) {
#pragma unroll
    for (int st = 16; st >= 1; st >>= 1)
#pragma unroll
        for (int i = 0; i < 8; ++i)
#pragma unroll
            for (int s = 0; s < 8; ++s)
                acc[i][s] += __shfl_xor_sync(0xffffffffu, acc[i][s], st);
    float o0 = 0.0f, o1 = 0.0f;
#pragma unroll
    for (int idx = 0; idx < 32; ++idx) {
        if (lane == idx) {
            o0 = acc[idx >> 3][idx & 7];
            o1 = acc[(idx >> 3) + 4][idx & 7];
        }
    }
    int i0 = lane >> 3, s0 = lane & 7;
    if (t0 + i0 < T_LEN)     dst[s0 * T_LEN + t0 + i0]     = o0;
    if (t0 + i0 + 4 < T_LEN) dst[s0 * T_LEN + t0 + i0 + 4] = o1;
}

__global__ void __launch_bounds__(256, 2)
pool_kernel(const float* __restrict__ S_e, const float* __restrict__ S_i) {
    __shared__ float shCe[SUB_NO * 1024];
    __shared__ float shCi[SUB_NO * 256];
    int tid = threadIdx.x;
    for (int idx = tid; idx < SUB_NO * 1024; idx += 256) {
        int s = idx >> 10, e = idx & 1023;
        shCe[idx] = (e < E_NUM) ? g_Ce[s * E_NUM + e] : 0.0f;
    }
    for (int idx = tid; idx < SUB_NO * 256; idx += 256) {
        int s = idx >> 8, e = idx & 255;
        shCi[idx] = (e < I_NUM) ? g_Ci[s * I_NUM + e] : 0.0f;
    }
    __syncthreads();

    int b = blockIdx.y;
    int warp = tid >> 5, lane = tid & 31;
    int t0 = blockIdx.x * 64 + warp * 8;
    if (t0 >= T_LEN) return;   // uniform per warp

    float acc[8][8];
    // ---- excitatory ----
#pragma unroll
    for (int i = 0; i < 8; ++i)
#pragma unroll
        for (int s = 0; s < 8; ++s) acc[i][s] = 0.0f;

    for (int k = 0; k < 1024; k += 32) {
        int e = k + lane;
        float cv[8];
#pragma unroll
        for (int s = 0; s < 8; ++s) cv[s] = shCe[s * 1024 + e];
        float sv[8];
#pragma unroll
        for (int i = 0; i < 8; ++i) {
            int t = t0 + i;
            sv[i] = (e < E_NUM && t < T_LEN)
                        ? S_e[(size_t)(b * T_LEN + t) * E_NUM + e] : 0.0f;
        }
#pragma unroll
        for (int i = 0; i < 8; ++i)
#pragma unroll
            for (int s = 0; s < 8; ++s)
                acc[i][s] = fmaf(sv[i], cv[s], acc[i][s]);
    }
    warp_reduce_write(acc, &g_syn_e[b * SUB_NO * T_LEN], t0, lane);

    // ---- inhibitory ----
#pragma unroll
    for (int i = 0; i < 8; ++i)
#pragma unroll
        for (int s = 0; s < 8; ++s) acc[i][s] = 0.0f;

    for (int k = 0; k < 256; k += 32) {
        int e = k + lane;
        float cv[8];
#pragma unroll
        for (int s = 0; s < 8; ++s) cv[s] = shCi[s * 256 + e];
        float sv[8];
#pragma unroll
        for (int i = 0; i < 8; ++i) {
            int t = t0 + i;
            sv[i] = (e < I_NUM && t < T_LEN)
                        ? S_i[(size_t)(b * T_LEN + t) * I_NUM + e] : 0.0f;
        }
#pragma unroll
        for (int i = 0; i < 8; ++i)
#pragma unroll
            for (int s = 0; s < 8; ++s)
                acc[i][s] = fmaf(sv[i], cv[s], acc[i][s]);
    }
    warp_reduce_write(acc, &g_syn_i[b * SUB_NO * T_LEN], t0, lane);
}

// ---------------- K3: causal conv + tanh + readout (compute-bound) ----------------
#define TC 512
#define XW (TC + T_NO)   // 712

__global__ void __launch_bounds__(256, 2)
conv_kernel(const float* __restrict__ W2,
            const float* __restrict__ b1,
            float* __restrict__ out) {
    __shared__ __align__(16) float sKe[T_NO * HID_NO];   // [tau][h]
    __shared__ __align__(16) float sKi[T_NO * HID_NO];
    __shared__ float sXe[XW], sXi[XW];
    __shared__ float sEw2[HID_NO], sB1[HID_NO];

    int tid = threadIdx.x;
    int bs = blockIdx.y;
    int b = bs >> 3, s = bs & 7;
    int t0 = blockIdx.x * TC;

    for (int idx = tid; idx < T_NO * HID_NO; idx += 256) {
        sKe[idx] = g_kern_e[s * T_NO * HID_NO + idx];
        sKi[idx] = g_kern_i[s * T_NO * HID_NO + idx];
    }
    for (int idx = tid; idx < XW; idx += 256) {
        int g = t0 - (T_NO - 1) + idx;
        bool ok = (g >= 0) && (g < T_LEN);
        sXe[idx] = ok ? g_syn_e[(b * SUB_NO + s) * T_LEN + g] : 0.0f;
        sXi[idx] = ok ? g_syn_i[(b * SUB_NO + s) * T_LEN + g] : 0.0f;
    }
    if (tid < HID_NO) {
        sEw2[tid] = expf(W2[s * HID_NO + tid]);
        sB1[tid]  = b1[s * HID_NO + tid];
    }
    __syncthreads();

    float2 acc0[8], acc1[8];
#pragma unroll
    for (int hp = 0; hp < 8; ++hp) {
        acc0[hp] = make_float2(0.0f, 0.0f);
        acc1[hp] = make_float2(0.0f, 0.0f);
    }

    int o0 = tid + (T_NO - 1);
    int o1 = tid + 256 + (T_NO - 1);

#pragma unroll 2
    for (int tau = 0; tau < T_NO; ++tau) {
        float xe0 = sXe[o0 - tau], xe1 = sXe[o1 - tau];
        float xi0 = sXi[o0 - tau], xi1 = sXi[o1 - tau];
        float2 ve0 = make_float2(xe0, xe0), ve1 = make_float2(xe1, xe1);
        float2 vi0 = make_float2(xi0, xi0), vi1 = make_float2(xi1, xi1);
        const float2* k_e = reinterpret_cast<const float2*>(&sKe[tau * HID_NO]);
        const float2* k_i = reinterpret_cast<const float2*>(&sKi[tau * HID_NO]);
#pragma unroll
        for (int hp = 0; hp < 8; ++hp) {
            float2 ke = k_e[hp], ki = k_i[hp];
            acc0[hp] = ffma2(ke, ve0, acc0[hp]);
            acc0[hp] = ffma2(ki, vi0, acc0[hp]);
            acc1[hp] = ffma2(ke, ve1, acc1[hp]);
            acc1[hp] = ffma2(ki, vi1, acc1[hp]);
        }
    }

    // epilogue: tanh + positive readout -> sub_out[b, t, s]
    {
        int t = t0 + tid;
        if (t < T_LEN) {
            float so = 0.0f;
#pragma unroll
            for (int hp = 0; hp < 8; ++hp) {
                so = fmaf(sEw2[2 * hp],     tanh_fast(acc0[hp].x + sB1[2 * hp]),     so);
                so = fmaf(sEw2[2 * hp + 1], tanh_fast(acc0[hp].y + sB1[2 * hp + 1]), so);
            }
            out[SUBOUT_OFF + (size_t)(b * T_LEN + t) * SUB_NO + s] = so;
        }
    }
    {
        int t = t0 + tid + 256;
        if (t < T_LEN) {
            float so = 0.0f;
#pragma unroll
            for (int hp = 0; hp < 8; ++hp) {
                so = fmaf(sEw2[2 * hp],     tanh_fast(acc1[hp].x + sB1[2 * hp]),     so);
                so = fmaf(sEw2[2 * hp + 1], tanh_fast(acc1[hp].y + sB1[2 * hp + 1]), so);
            }
            out[SUBOUT_OFF + (size_t)(b * T_LEN + t) * SUB_NO + s] = so;
        }
    }
}

// ---------------- K4: final = sum_s sub_out + V_o ----------------
__global__ void final_kernel(const float* __restrict__ V_o, float* __restrict__ out) {
    int idx = blockIdx.x * blockDim.x + threadIdx.x;
    if (idx >= B_NO * T_LEN) return;
    const float* p = &out[SUBOUT_OFF + (size_t)idx * SUB_NO];
    float sum = V_o[0];
#pragma unroll
    for (int s = 0; s < SUB_NO; ++s) sum += p[s];
    out[FINAL_OFF + idx] = sum;
}

// ---------------- launch ----------------
extern "C" void kernel_launch(void* const* d_in, const int* in_sizes, int n_in,
                              void* d_out, int out_size) {
    (void)in_sizes; (void)n_in; (void)out_size;
    const float* S_e   = (const float*)d_in[0];
    const float* S_i   = (const float*)d_in[1];
    const float* Es    = (const float*)d_in[2];
    const float* Is    = (const float*)d_in[3];
    const float* W_e   = (const float*)d_in[4];
    const float* W_i   = (const float*)d_in[5];
    const float* W2    = (const float*)d_in[6];
    const float* b1    = (const float*)d_in[7];
    const float* Cer   = (const float*)d_in[8];
    const float* Cir   = (const float*)d_in[9];
    const float* V_o   = (const float*)d_in[10];
    float* out = (float*)d_out;

    softmax_kernel<<<(E_NUM + I_NUM + 255) / 256, 256>>>(Cer, Cir, Es, Is, out);
    kern_kernel<<<T_NO, 128>>>(W_e, W_i);

    dim3 pg((T_LEN + 63) / 64, B_NO);      // 157 x 8
    pool_kernel<<<pg, 256>>>(S_e, S_i);

    dim3 cg((T_LEN + TC - 1) / TC, B_NO * SUB_NO);  // 20 x 64
    conv_kernel<<<cg, 256>>>(W2, b1, out);

    final_kernel<<<(B_NO * T_LEN + 255) / 256, 256>>>(V_o, out);
}